// round 10
// baseline (speedup 1.0000x reference)
#include <cuda_runtime.h>
#include <math.h>

#define BD 8
#define SD 128
#define ED 50
#define DD 300
#define DED 50
#define EPSV 1e-6f

#define NODE_ELEMS (BD*SD*DD)          // 307200
#define EDGE_ELEMS (BD*SD*SD*DED)      // 6553600

#define AK 352        // padded K for combined refine GEMM (50 diag + 300 node + 2 pad)
#define WCC 128       // padded cols: 0..49 = J, 64..113 = I

// ---- scratch (no allocation allowed) ----
__device__ float g_wsum[BD*SD*SD];       // 131072  collapsed adjacency
__device__ float g_y[BD*SD*DD];          // 307200  x @ W_w
__device__ float g_A[BD*SD*AK];          // 360448  [diag | node] packed rows
__device__ float g_Wc[AK*WCC];           // 45056   combined refine weights
__device__ float g_tJ[BD*SD*DED];        // 51200
__device__ float g_tI[BD*SD*DED];        // 51200

// ============================================================
// k1: Wsum[b,i,j] = (1/E) * sum_e softmax[b,i,j,e] + (i==j)
// ============================================================
__global__ __launch_bounds__(256) void k_wsum(const float* __restrict__ wps) {
    __shared__ float tile[128 * ED];
    int rbase = blockIdx.x * 128;
    const float* src = wps + (size_t)rbase * ED;
    for (int t = threadIdx.x; t < 128 * ED; t += 256) tile[t] = src[t];
    __syncthreads();
    if (threadIdx.x < 128) {
        int r = threadIdx.x;
        float s = 0.f;
        #pragma unroll
        for (int e = 0; e < ED; e++) s += tile[r * ED + e];
        int row = rbase + r;
        int j = row & 127;
        int i = (row >> 7) & 127;
        g_wsum[row] = s * (1.0f / (float)ED) + (i == j ? 1.0f : 0.0f);
    }
}

// ============================================================
// k_prep: build g_Wc (combined refine weights) and diag part of g_A.
//   Wc[k][c], c<50:      J -> rW[k<50 ? 50+k : 100+k][c]
//             64<=c<114: I -> rW[k<50 ? 100+k : 400+k][c-64]
//             else 0;  k>=350 -> 0
//   A[r][0:50] = wadj[b,s,s,:]
//   total work = 352*128 + 1024*50 = 96256 = 376 blocks * 256
// ============================================================
__global__ __launch_bounds__(256) void k_prep(const float* __restrict__ wadj,
                                              const float* __restrict__ rW) {
    int idx = blockIdx.x * 256 + threadIdx.x;
    if (idx < AK * WCC) {
        int k = idx >> 7;
        int c = idx & 127;
        float v = 0.f;
        if (k < 350) {
            if (c < DED) {
                int row = (k < 50) ? (50 + k) : (100 + k);
                v = rW[(size_t)row * DED + c];
            } else if (c >= 64 && c < 64 + DED) {
                int row = (k < 50) ? (100 + k) : (400 + k);
                v = rW[(size_t)row * DED + (c - 64)];
            }
        }
        g_Wc[idx] = v;
    } else {
        int t = idx - AK * WCC;          // < 51200
        int r = t / DED, e = t % DED;
        int b = r >> 7, s = r & 127;
        g_A[(size_t)r * AK + e] = wadj[((size_t)(b * SD + s) * SD + s) * ED + e];
    }
}

// ============================================================
// k2a: y = x @ W_w.  4 rows/block (grid 256), 96 threads, 75 active.
//   thread: 4 rows x 4 cols; per d: 1 LDS128 + 1 LDG128 + 16 FMA
// ============================================================
__global__ __launch_bounds__(96) void k_xw(const float* __restrict__ x,
                                           const float* __restrict__ Ww) {
    __shared__ __align__(16) float xsT[DD][4];   // transposed 4-row tile
    int rbase = blockIdx.x * 4;
    for (int t = threadIdx.x; t < 4 * DD; t += 96) {
        int r = t / DD, d = t % DD;
        xsT[d][r] = x[(size_t)(rbase + r) * DD + d];
    }
    __syncthreads();
    int c0 = threadIdx.x * 4;
    if (c0 >= DD) return;
    float acc[4][4];
    #pragma unroll
    for (int r = 0; r < 4; r++)
        #pragma unroll
        for (int k = 0; k < 4; k++) acc[r][k] = 0.f;
    #pragma unroll 4
    for (int d = 0; d < DD; d++) {
        float4 xa = *(const float4*)&xsT[d][0];
        float4 w  = *(const float4*)&Ww[(size_t)d * DD + c0];
        acc[0][0] += xa.x * w.x; acc[0][1] += xa.x * w.y; acc[0][2] += xa.x * w.z; acc[0][3] += xa.x * w.w;
        acc[1][0] += xa.y * w.x; acc[1][1] += xa.y * w.y; acc[1][2] += xa.y * w.z; acc[1][3] += xa.y * w.w;
        acc[2][0] += xa.z * w.x; acc[2][1] += xa.z * w.y; acc[2][2] += xa.z * w.z; acc[2][3] += xa.z * w.w;
        acc[3][0] += xa.w * w.x; acc[3][1] += xa.w * w.y; acc[3][2] += xa.w * w.z; acc[3][3] += xa.w * w.w;
    }
    #pragma unroll
    for (int r = 0; r < 4; r++) {
        float4 o = make_float4(acc[r][0], acc[r][1], acc[r][2], acc[r][3]);
        *(float4*)&g_y[(size_t)(rbase + r) * DD + c0] = o;
    }
}

// ============================================================
// k2b: h = Wsum @ y + W_b -> LayerNorm (unbiased +eps) -> ReLU
//   8 rows/block (grid 128), 320 threads. node -> g_A[:,50:350] + node_out
// ============================================================
__global__ __launch_bounds__(320) void k_gcn_ln(const float* __restrict__ Wb,
                                                const float* __restrict__ lna,
                                                const float* __restrict__ lnb,
                                                float* __restrict__ node_out) {
    __shared__ __align__(16) float wrT[SD][8];   // transposed wsum tile
    __shared__ float redA[10];
    __shared__ float redB[10];
    __shared__ float bc[2];
    int gibase = blockIdx.x * 8;
    int b = gibase >> 7;
    for (int t = threadIdx.x; t < 8 * SD; t += 320) {
        int r = t >> 7, j = t & 127;
        wrT[j][r] = g_wsum[(size_t)gibase * SD + r * SD + j];
    }
    __syncthreads();

    int o = threadIdx.x;
    float acc[8];
    #pragma unroll
    for (int r = 0; r < 8; r++) acc[r] = 0.f;
    if (o < DD) {
        const float* yb = g_y + (size_t)(b * SD) * DD + o;
        #pragma unroll 4
        for (int j = 0; j < SD; j++) {
            float v = yb[(size_t)j * DD];
            float4 w0 = *(const float4*)&wrT[j][0];
            float4 w1 = *(const float4*)&wrT[j][4];
            acc[0] += w0.x * v; acc[1] += w0.y * v; acc[2] += w0.z * v; acc[3] += w0.w * v;
            acc[4] += w1.x * v; acc[5] += w1.y * v; acc[6] += w1.z * v; acc[7] += w1.w * v;
        }
        float bias = Wb[o];
        #pragma unroll
        for (int r = 0; r < 8; r++) acc[r] += bias;
    }
    float la = (o < DD) ? lna[o] : 0.f;
    float lb = (o < DD) ? lnb[o] : 0.f;
    int lane = threadIdx.x & 31, wid = threadIdx.x >> 5;

    for (int r = 0; r < 8; r++) {
        float h = (o < DD) ? acc[r] : 0.f;
        float s1 = h, s2 = h * h;
        #pragma unroll
        for (int off = 16; off > 0; off >>= 1) {
            s1 += __shfl_down_sync(0xffffffffu, s1, off);
            s2 += __shfl_down_sync(0xffffffffu, s2, off);
        }
        if (lane == 0) { redA[wid] = s1; redB[wid] = s2; }
        __syncthreads();
        if (threadIdx.x == 0) {
            float t1 = 0.f, t2 = 0.f;
            #pragma unroll
            for (int w = 0; w < 10; w++) { t1 += redA[w]; t2 += redB[w]; }
            bc[0] = t1; bc[1] = t2;
        }
        __syncthreads();
        float mean = bc[0] * (1.0f / (float)DD);
        float var = (bc[1] - (float)DD * mean * mean) * (1.0f / (float)(DD - 1));
        var = fmaxf(var, 0.f);
        float inv = 1.0f / (sqrtf(var) + EPSV);
        if (o < DD) {
            float nv = la * (acc[r] - mean) * inv + lb;
            nv = fmaxf(nv, 0.f);
            int gi = gibase + r;
            g_A[(size_t)gi * AK + 50 + o] = nv;
            if (node_out) node_out[(size_t)gi * DD + o] = nv;
        }
        __syncthreads();
    }
}

// ============================================================
// k3: combined refine GEMM  [1024 x 352] @ [352 x 128] -> tJ | tI
//   grid 128, 256 thr, tile 8 rows x 128 cols, thread = 1 row x 4 cols.
//   smem-staged K chunks of 32.
// ============================================================
__global__ __launch_bounds__(256) void k_terms() {
    __shared__ __align__(16) float Ws[32][WCC];   // 16 KB
    __shared__ float As[8][32];                   // 1 KB
    int rbase = blockIdx.x * 8;
    int r = threadIdx.x >> 5;
    int lane = threadIdx.x & 31;
    int c0 = lane * 4;
    float a0 = 0.f, a1 = 0.f, a2 = 0.f, a3 = 0.f;

    for (int k0 = 0; k0 < AK; k0 += 32) {
        __syncthreads();
        #pragma unroll
        for (int p = 0; p < 4; p++) {
            int kk = r + p * 8;
            *(float4*)&Ws[kk][c0] = *(const float4*)&g_Wc[(size_t)(k0 + kk) * WCC + c0];
        }
        As[r][lane] = g_A[(size_t)(rbase + r) * AK + k0 + lane];
        __syncthreads();
        #pragma unroll
        for (int kk = 0; kk < 32; kk++) {
            float a = As[r][kk];
            float4 w = *(const float4*)&Ws[kk][c0];
            a0 += a * w.x; a1 += a * w.y; a2 += a * w.z; a3 += a * w.w;
        }
    }

    int row = rbase + r;
    if (c0 < DED) {
        float* dst = g_tJ + (size_t)row * DED + c0;
        dst[0] = a0;
        if (c0 + 1 < DED) dst[1] = a1;
        if (c0 + 2 < DED) dst[2] = a2;
        if (c0 + 3 < DED) dst[3] = a3;
    } else if (c0 >= 64 && c0 < 64 + DED) {
        int cc = c0 - 64;
        float* dst = g_tI + (size_t)row * DED + cc;
        dst[0] = a0;
        if (cc + 1 < DED) dst[1] = a1;
        if (cc + 2 < DED) dst[2] = a2;
        if (cc + 3 < DED) dst[3] = a3;
    }
}

// ============================================================
// k4: edge_out[row,o] = adj[row,:50] @ Wa + termJ[b,j] + termI[b,i] + rb
//   Tile: 64 rows x 64 cols (50 valid), 128 threads, each thread 4x8.
// ============================================================
__global__ __launch_bounds__(128) void k_edge(const float* __restrict__ wadj,
                                              const float* __restrict__ rW,
                                              const float* __restrict__ rb,
                                              float* __restrict__ eout) {
    __shared__ float adjS[64][52];
    __shared__ __align__(16) float WaS[ED][64];
    __shared__ float tJS[64][DED];
    __shared__ float cI[64];
    int rbase = blockIdx.x * 64;
    int b = rbase >> 14;
    int i = (rbase >> 7) & 127;
    int jbase = rbase & 127;

    for (int t = threadIdx.x; t < 64 * ED; t += 128) {
        int r = t / ED, e = t % ED;
        adjS[r][e] = wadj[(size_t)rbase * ED + t];
    }
    for (int t = threadIdx.x; t < ED * 64; t += 128) {
        int e = t >> 6, o = t & 63;
        WaS[e][o] = (o < DED) ? rW[(size_t)e * DED + o] : 0.f;
    }
    for (int t = threadIdx.x; t < 64 * DED; t += 128)
        tJS[t / DED][t % DED] = g_tJ[(size_t)(b * SD + jbase) * DED + t];
    if (threadIdx.x < 64) {
        int o = threadIdx.x;
        cI[o] = (o < DED) ? (g_tI[(size_t)(b * SD + i) * DED + o] + rb[o]) : 0.f;
    }
    __syncthreads();

    int cg = threadIdx.x & 7;
    int rg = threadIdx.x >> 3;
    int r0 = rg * 4;
    int c0 = cg * 8;

    float acc[4][8];
    #pragma unroll
    for (int r = 0; r < 4; r++)
        #pragma unroll
        for (int k = 0; k < 8; k++) acc[r][k] = 0.f;

    #pragma unroll 2
    for (int e = 0; e < ED; e++) {
        float a[4];
        #pragma unroll
        for (int r = 0; r < 4; r++) a[r] = adjS[r0 + r][e];
        float4 w0 = *(const float4*)&WaS[e][c0];
        float4 w1 = *(const float4*)&WaS[e][c0 + 4];
        float w[8] = {w0.x, w0.y, w0.z, w0.w, w1.x, w1.y, w1.z, w1.w};
        #pragma unroll
        for (int r = 0; r < 4; r++)
            #pragma unroll
            for (int k = 0; k < 8; k++) acc[r][k] += a[r] * w[k];
    }

    #pragma unroll
    for (int r = 0; r < 4; r++) {
        int row = rbase + r0 + r;
        float* orow = eout + (size_t)row * DED;
        const float* tjr = tJS[r0 + r];
        #pragma unroll
        for (int k = 0; k < 8; k++) {
            int o = c0 + k;
            if (o < DED) orow[o] = acc[r][k] + tjr[o] + cI[o];
        }
    }
}

// ============================================================
extern "C" void kernel_launch(void* const* d_in, const int* in_sizes, int n_in,
                              void* d_out, int out_size) {
    const float* wps  = (const float*)d_in[0];   // [B,S,S,E]
    const float* wadj = (const float*)d_in[1];   // [B,S,S,E]
    const float* x    = (const float*)d_in[2];   // [B,S,D]
    // d_in[3] self_loop: identity by construction -> unused
    const float* Ww   = (const float*)d_in[4];   // [D,D]
    const float* Wb   = (const float*)d_in[5];   // [D]
    const float* lna  = (const float*)d_in[6];   // [D]
    const float* lnb  = (const float*)d_in[7];   // [D]
    const float* rW   = (const float*)d_in[8];   // [750,50]
    const float* rb   = (const float*)d_in[9];   // [50]

    float* out = (float*)d_out;
    float* node_out = nullptr;
    float* edge_out;
    if (out_size >= NODE_ELEMS + EDGE_ELEMS) {
        node_out = out;
        edge_out = out + NODE_ELEMS;
    } else {
        edge_out = out + (out_size - EDGE_ELEMS);  // edge-only fallback
    }

    k_wsum  <<<BD*SD*SD/128, 256>>>(wps);
    k_prep  <<<(AK*WCC + BD*SD*DED)/256, 256>>>(wadj, rW);
    k_xw    <<<BD*SD/4, 96>>>(x, Ww);
    k_gcn_ln<<<BD*SD/8, 320>>>(Wb, lna, lnb, node_out);
    k_terms <<<BD*SD/8, 256>>>();
    k_edge  <<<BD*SD*SD/64, 128>>>(wadj, rW, rb, edge_out);
}

// round 12
// speedup vs baseline: 1.2096x; 1.2096x over previous
#include <cuda_runtime.h>
#include <math.h>

#define BD 8
#define SD 128
#define ED 50
#define DD 300
#define DED 50
#define EPSV 1e-6f

#define NODE_ELEMS (BD*SD*DD)          // 307200
#define EDGE_ELEMS (BD*SD*SD*DED)      // 6553600

#define AK 352        // padded K for combined refine GEMM (50 diag + 300 node + 2 pad)
#define WCC 128       // padded cols: 0..49 = J, 64..113 = I

// ---- scratch (no allocation allowed) ----
__device__ float g_wsum[BD*SD*SD];       // collapsed adjacency
__device__ float g_y[BD*SD*DD];          // x @ W_w
__device__ float g_h[BD*SD*DD];          // Wsum @ y (pre-LN)
__device__ float g_A[BD*SD*AK];          // [diag | node] packed rows
__device__ float g_Wc[AK*WCC];           // combined refine weights
__device__ float g_tJ[BD*SD*DED];
__device__ float g_tI[BD*SD*DED];

// ============================================================
// k0: fused wsum + prep.
//   blocks [0,1024): Wsum[b,i,j] = mean_e softmax + (i==j)
//   blocks [1024,1400): build g_Wc and diag part of g_A
// ============================================================
__global__ __launch_bounds__(256) void k_wsum_prep(const float* __restrict__ wps,
                                                   const float* __restrict__ wadj,
                                                   const float* __restrict__ rW) {
    if (blockIdx.x < 1024) {
        __shared__ float tile[128 * ED];
        int rbase = blockIdx.x * 128;
        const float* src = wps + (size_t)rbase * ED;
        for (int t = threadIdx.x; t < 128 * ED; t += 256) tile[t] = src[t];
        __syncthreads();
        if (threadIdx.x < 128) {
            int r = threadIdx.x;
            float s = 0.f;
            #pragma unroll
            for (int e = 0; e < ED; e++) s += tile[r * ED + e];
            int row = rbase + r;
            int j = row & 127;
            int i = (row >> 7) & 127;
            g_wsum[row] = s * (1.0f / (float)ED) + (i == j ? 1.0f : 0.0f);
        }
    } else {
        int idx = (blockIdx.x - 1024) * 256 + threadIdx.x;
        if (idx < AK * WCC) {
            int k = idx >> 7;
            int c = idx & 127;
            float v = 0.f;
            if (k < 350) {
                if (c < DED) {
                    int row = (k < 50) ? (50 + k) : (100 + k);
                    v = rW[(size_t)row * DED + c];
                } else if (c >= 64 && c < 64 + DED) {
                    int row = (k < 50) ? (100 + k) : (400 + k);
                    v = rW[(size_t)row * DED + (c - 64)];
                }
            }
            g_Wc[idx] = v;
        } else if (idx < AK * WCC + BD * SD * DED) {
            int t = idx - AK * WCC;
            int r = t / DED, e = t % DED;
            int b = r >> 7, s = r & 127;
            g_A[(size_t)r * AK + e] = wadj[((size_t)(b * SD + s) * SD + s) * ED + e];
        }
    }
}

// ============================================================
// k1: y = x @ W_w.  Tile 16 rows x 100 cols, grid 192, 224 thr.
//   thread = 4 rows x 2 cols; per d: 1 LDS128 + 1 LDG64 + 8 FMA.
// ============================================================
__global__ __launch_bounds__(224) void k_xw(const float* __restrict__ x,
                                            const float* __restrict__ Ww) {
    __shared__ __align__(16) float xsT[DD][20];   // [d][row], padded stride
    int rbase = (blockIdx.x / 3) * 16;
    int cbase = (blockIdx.x % 3) * 100;
    for (int t = threadIdx.x; t < 16 * DD; t += 224) {
        int r = t / DD, d = t % DD;
        xsT[d][r] = x[(size_t)(rbase + r) * DD + d];
    }
    __syncthreads();
    int tr = threadIdx.x / 50;     // 0..3 (tid<200)
    int tc = threadIdx.x % 50;
    if (threadIdx.x >= 200) return;
    int c = cbase + tc * 2;
    float acc[4][2];
    #pragma unroll
    for (int r = 0; r < 4; r++) { acc[r][0] = 0.f; acc[r][1] = 0.f; }
    #pragma unroll 4
    for (int d = 0; d < DD; d++) {
        float4 xa = *(const float4*)&xsT[d][tr * 4];
        float2 w  = *(const float2*)&Ww[(size_t)d * DD + c];
        acc[0][0] += xa.x * w.x; acc[0][1] += xa.x * w.y;
        acc[1][0] += xa.y * w.x; acc[1][1] += xa.y * w.y;
        acc[2][0] += xa.z * w.x; acc[2][1] += xa.z * w.y;
        acc[3][0] += xa.w * w.x; acc[3][1] += xa.w * w.y;
    }
    #pragma unroll
    for (int r = 0; r < 4; r++) {
        float2 o = make_float2(acc[r][0], acc[r][1]);
        *(float2*)&g_y[(size_t)(rbase + tr * 4 + r) * DD + c] = o;
    }
}

// ============================================================
// k2: h = Wsum @ y.  Tile 8 rows x 100 cols, grid 384, 128 thr.
//   thread = 4 rows x 2 cols; per j: 1 LDS128 + 1 LDG64 + 8 FMA.
// ============================================================
__global__ __launch_bounds__(128) void k_gemm2() {
    __shared__ __align__(16) float wrT[SD][8];    // [j][row]
    int rb = (blockIdx.x / 3) * 8;
    int cbase = (blockIdx.x % 3) * 100;
    int b = rb >> 7;
    for (int t = threadIdx.x; t < 8 * SD; t += 128) {
        int r = t >> 7, j = t & 127;
        wrT[j][r] = g_wsum[(size_t)(rb + r) * SD + j];
    }
    __syncthreads();
    int tr = threadIdx.x / 50;     // 0..1 (tid<100)
    int tc = threadIdx.x % 50;
    if (threadIdx.x >= 100) return;
    int c = cbase + tc * 2;
    const float* yb = g_y + (size_t)(b * SD) * DD + c;
    float acc[4][2];
    #pragma unroll
    for (int r = 0; r < 4; r++) { acc[r][0] = 0.f; acc[r][1] = 0.f; }
    #pragma unroll 4
    for (int j = 0; j < SD; j++) {
        float4 w = *(const float4*)&wrT[j][tr * 4];
        float2 yv = *(const float2*)&yb[(size_t)j * DD];
        acc[0][0] += w.x * yv.x; acc[0][1] += w.x * yv.y;
        acc[1][0] += w.y * yv.x; acc[1][1] += w.y * yv.y;
        acc[2][0] += w.z * yv.x; acc[2][1] += w.z * yv.y;
        acc[3][0] += w.w * yv.x; acc[3][1] += w.w * yv.y;
    }
    #pragma unroll
    for (int r = 0; r < 4; r++) {
        float2 o = make_float2(acc[r][0], acc[r][1]);
        *(float2*)&g_h[(size_t)(rb + tr * 4 + r) * DD + c] = o;
    }
}

// ============================================================
// k3: LayerNorm (unbiased std + eps) + ReLU per row; bias added here.
//   grid 1024 (one row/block), 320 thr.
// ============================================================
__global__ __launch_bounds__(320) void k_ln(const float* __restrict__ Wb,
                                            const float* __restrict__ lna,
                                            const float* __restrict__ lnb,
                                            float* __restrict__ node_out) {
    __shared__ float redA[10];
    __shared__ float redB[10];
    __shared__ float bc[2];
    int row = blockIdx.x;
    int o = threadIdx.x;
    float val = 0.f;
    if (o < DD) val = g_h[(size_t)row * DD + o] + Wb[o];
    float s1 = val, s2 = val * val;
    int lane = threadIdx.x & 31, wid = threadIdx.x >> 5;
    #pragma unroll
    for (int off = 16; off > 0; off >>= 1) {
        s1 += __shfl_down_sync(0xffffffffu, s1, off);
        s2 += __shfl_down_sync(0xffffffffu, s2, off);
    }
    if (lane == 0) { redA[wid] = s1; redB[wid] = s2; }
    __syncthreads();
    if (threadIdx.x == 0) {
        float t1 = 0.f, t2 = 0.f;
        #pragma unroll
        for (int w = 0; w < 10; w++) { t1 += redA[w]; t2 += redB[w]; }
        bc[0] = t1; bc[1] = t2;
    }
    __syncthreads();
    float mean = bc[0] * (1.0f / (float)DD);
    float var = (bc[1] - (float)DD * mean * mean) * (1.0f / (float)(DD - 1));
    var = fmaxf(var, 0.f);
    float inv = 1.0f / (sqrtf(var) + EPSV);
    if (o < DD) {
        float nv = lna[o] * (val - mean) * inv + lnb[o];
        nv = fmaxf(nv, 0.f);
        g_A[(size_t)row * AK + 50 + o] = nv;
        if (node_out) node_out[(size_t)row * DD + o] = nv;
    }
}

// ============================================================
// k4: combined refine GEMM  [1024 x 352] @ [352 x 128] -> tJ | tI
//   grid 128, 256 thr, tile 8 rows x 128 cols, thread = 1 row x 4 cols.
// ============================================================
__global__ __launch_bounds__(256) void k_terms() {
    __shared__ __align__(16) float Ws[32][WCC];   // 16 KB
    __shared__ float As[8][32];                   // 1 KB
    int rbase = blockIdx.x * 8;
    int r = threadIdx.x >> 5;
    int lane = threadIdx.x & 31;
    int c0 = lane * 4;
    float a0 = 0.f, a1 = 0.f, a2 = 0.f, a3 = 0.f;

    for (int k0 = 0; k0 < AK; k0 += 32) {
        __syncthreads();
        #pragma unroll
        for (int p = 0; p < 4; p++) {
            int kk = r + p * 8;
            *(float4*)&Ws[kk][c0] = *(const float4*)&g_Wc[(size_t)(k0 + kk) * WCC + c0];
        }
        As[r][lane] = g_A[(size_t)(rbase + r) * AK + k0 + lane];
        __syncthreads();
        #pragma unroll
        for (int kk = 0; kk < 32; kk++) {
            float a = As[r][kk];
            float4 w = *(const float4*)&Ws[kk][c0];
            a0 += a * w.x; a1 += a * w.y; a2 += a * w.z; a3 += a * w.w;
        }
    }

    int row = rbase + r;
    if (c0 < DED) {
        float* dst = g_tJ + (size_t)row * DED + c0;
        dst[0] = a0;
        if (c0 + 1 < DED) dst[1] = a1;
        if (c0 + 2 < DED) dst[2] = a2;
        if (c0 + 3 < DED) dst[3] = a3;
    } else if (c0 >= 64 && c0 < 64 + DED) {
        int cc = c0 - 64;
        float* dst = g_tI + (size_t)row * DED + cc;
        dst[0] = a0;
        if (cc + 1 < DED) dst[1] = a1;
        if (cc + 2 < DED) dst[2] = a2;
        if (cc + 3 < DED) dst[3] = a3;
    }
}

// ============================================================
// k5: edge_out[row,o] = adj[row,:50] @ Wa + termJ[b,j] + termI[b,i] + rb
//   Tile: 64 rows x 64 cols (50 valid), 128 threads, thread = 4x8.
// ============================================================
__global__ __launch_bounds__(128) void k_edge(const float* __restrict__ wadj,
                                              const float* __restrict__ rW,
                                              const float* __restrict__ rb,
                                              float* __restrict__ eout) {
    __shared__ float adjS[64][52];
    __shared__ __align__(16) float WaS[ED][64];
    __shared__ float tJS[64][DED];
    __shared__ float cI[64];
    int rbase = blockIdx.x * 64;
    int b = rbase >> 14;
    int i = (rbase >> 7) & 127;
    int jbase = rbase & 127;

    for (int t = threadIdx.x; t < 64 * ED; t += 128) {
        int r = t / ED, e = t % ED;
        adjS[r][e] = wadj[(size_t)rbase * ED + t];
    }
    for (int t = threadIdx.x; t < ED * 64; t += 128) {
        int e = t >> 6, o = t & 63;
        WaS[e][o] = (o < DED) ? rW[(size_t)e * DED + o] : 0.f;
    }
    for (int t = threadIdx.x; t < 64 * DED; t += 128)
        tJS[t / DED][t % DED] = g_tJ[(size_t)(b * SD + jbase) * DED + t];
    if (threadIdx.x < 64) {
        int o = threadIdx.x;
        cI[o] = (o < DED) ? (g_tI[(size_t)(b * SD + i) * DED + o] + rb[o]) : 0.f;
    }
    __syncthreads();

    int cg = threadIdx.x & 7;
    int rg = threadIdx.x >> 3;
    int r0 = rg * 4;
    int c0 = cg * 8;

    float acc[4][8];
    #pragma unroll
    for (int r = 0; r < 4; r++)
        #pragma unroll
        for (int k = 0; k < 8; k++) acc[r][k] = 0.f;

    #pragma unroll 2
    for (int e = 0; e < ED; e++) {
        float a[4];
        #pragma unroll
        for (int r = 0; r < 4; r++) a[r] = adjS[r0 + r][e];
        float4 w0 = *(const float4*)&WaS[e][c0];
        float4 w1 = *(const float4*)&WaS[e][c0 + 4];
        float w[8] = {w0.x, w0.y, w0.z, w0.w, w1.x, w1.y, w1.z, w1.w};
        #pragma unroll
        for (int r = 0; r < 4; r++)
            #pragma unroll
            for (int k = 0; k < 8; k++) acc[r][k] += a[r] * w[k];
    }

    #pragma unroll
    for (int r = 0; r < 4; r++) {
        int row = rbase + r0 + r;
        float* orow = eout + (size_t)row * DED;
        const float* tjr = tJS[r0 + r];
        #pragma unroll
        for (int k = 0; k < 8; k++) {
            int o = c0 + k;
            if (o < DED) orow[o] = acc[r][k] + tjr[o] + cI[o];
        }
    }
}

// ============================================================
extern "C" void kernel_launch(void* const* d_in, const int* in_sizes, int n_in,
                              void* d_out, int out_size) {
    const float* wps  = (const float*)d_in[0];   // [B,S,S,E]
    const float* wadj = (const float*)d_in[1];   // [B,S,S,E]
    const float* x    = (const float*)d_in[2];   // [B,S,D]
    // d_in[3] self_loop: identity by construction -> unused
    const float* Ww   = (const float*)d_in[4];   // [D,D]
    const float* Wb   = (const float*)d_in[5];   // [D]
    const float* lna  = (const float*)d_in[6];   // [D]
    const float* lnb  = (const float*)d_in[7];   // [D]
    const float* rW   = (const float*)d_in[8];   // [750,50]
    const float* rb   = (const float*)d_in[9];   // [50]

    float* out = (float*)d_out;
    float* node_out = nullptr;
    float* edge_out;
    if (out_size >= NODE_ELEMS + EDGE_ELEMS) {
        node_out = out;
        edge_out = out + NODE_ELEMS;
    } else {
        edge_out = out + (out_size - EDGE_ELEMS);  // edge-only fallback
    }

    int prep_blocks = (AK * WCC + BD * SD * DED + 255) / 256;   // 376
    k_wsum_prep<<<1024 + prep_blocks, 256>>>(wps, wadj, rW);
    k_xw    <<<(BD*SD/16)*3, 224>>>(x, Ww);
    k_gemm2 <<<(BD*SD/8)*3, 128>>>();
    k_ln    <<<BD*SD, 320>>>(Wb, lna, lnb, node_out);
    k_terms <<<BD*SD/8, 256>>>();
    k_edge  <<<BD*SD*SD/64, 128>>>(wadj, rW, rb, edge_out);
}

// round 13
// speedup vs baseline: 1.3550x; 1.1202x over previous
#include <cuda_runtime.h>
#include <math.h>

#define BD 8
#define SD 128
#define ED 50
#define DD 300
#define DED 50
#define EPSV 1e-6f

#define NODE_ELEMS (BD*SD*DD)          // 307200
#define EDGE_ELEMS (BD*SD*SD*DED)      // 6553600

#define AK 352        // padded K for combined refine GEMM (50 diag + 300 node + 2 pad)
#define WCC 128       // padded cols: 0..49 = J, 64..113 = I

// ---- scratch (no allocation allowed) ----
__device__ float g_wsum[BD*SD*SD];       // collapsed adjacency
__device__ float g_y[BD*SD*DD];          // x @ W_w
__device__ float g_A[BD*SD*AK];          // [diag | node] packed rows
__device__ float g_Wc[AK*WCC];           // combined refine weights
__device__ float g_tJ[BD*SD*DED];
__device__ float g_tI[BD*SD*DED];

#define PREP_BLOCKS 376   // ceil((AK*WCC + BD*SD*DED)/256) = (45056+51200)/256
#define XW_BLOCKS   192   // (BD*SD/16)*3

// ============================================================
// k_front: three independent jobs in one launch.
//   blocks [0,1024):        Wsum[b,i,j] = mean_e softmax + (i==j)
//   blocks [1024,1400):     build g_Wc and diag part of g_A
//   blocks [1400,1592):     y = x @ W_w  (tile 16 rows x 100 cols)
// ============================================================
__global__ __launch_bounds__(256) void k_front(const float* __restrict__ wps,
                                               const float* __restrict__ wadj,
                                               const float* __restrict__ rW,
                                               const float* __restrict__ x,
                                               const float* __restrict__ Ww) {
    __shared__ __align__(16) float sm[6400];     // 25.6 KB, shared by branches
    if (blockIdx.x < 1024) {
        // ---- wsum ----
        int rbase = blockIdx.x * 128;
        const float* src = wps + (size_t)rbase * ED;
        for (int t = threadIdx.x; t < 128 * ED; t += 256) sm[t] = src[t];
        __syncthreads();
        if (threadIdx.x < 128) {
            int r = threadIdx.x;
            float s = 0.f;
            #pragma unroll
            for (int e = 0; e < ED; e++) s += sm[r * ED + e];
            int row = rbase + r;
            int j = row & 127;
            int i = (row >> 7) & 127;
            g_wsum[row] = s * (1.0f / (float)ED) + (i == j ? 1.0f : 0.0f);
        }
    } else if (blockIdx.x < 1024 + PREP_BLOCKS) {
        // ---- Wc + diag(A) prep ----
        int idx = (blockIdx.x - 1024) * 256 + threadIdx.x;
        if (idx < AK * WCC) {
            int k = idx >> 7;
            int c = idx & 127;
            float v = 0.f;
            if (k < 350) {
                if (c < DED) {
                    int row = (k < 50) ? (50 + k) : (100 + k);
                    v = rW[(size_t)row * DED + c];
                } else if (c >= 64 && c < 64 + DED) {
                    int row = (k < 50) ? (100 + k) : (400 + k);
                    v = rW[(size_t)row * DED + (c - 64)];
                }
            }
            g_Wc[idx] = v;
        } else if (idx < AK * WCC + BD * SD * DED) {
            int t = idx - AK * WCC;
            int r = t / DED, e = t % DED;
            int b = r >> 7, s = r & 127;
            g_A[(size_t)r * AK + e] = wadj[((size_t)(b * SD + s) * SD + s) * ED + e];
        }
    } else {
        // ---- xw: y = x @ W_w, tile 16 rows x 100 cols ----
        float* xsT = sm;                          // [d][r] stride 20, 6000 floats
        int bxw = blockIdx.x - (1024 + PREP_BLOCKS);
        int rbase = (bxw / 3) * 16;
        int cbase = (bxw % 3) * 100;
        for (int t = threadIdx.x; t < 16 * DD; t += 256) {
            int r = t / DD, d = t % DD;
            xsT[d * 20 + r] = x[(size_t)(rbase + r) * DD + d];
        }
        __syncthreads();
        if (threadIdx.x >= 200) return;
        int tr = threadIdx.x / 50;     // 0..3
        int tc = threadIdx.x % 50;
        int c = cbase + tc * 2;
        float acc[4][2];
        #pragma unroll
        for (int r = 0; r < 4; r++) { acc[r][0] = 0.f; acc[r][1] = 0.f; }
        #pragma unroll 4
        for (int d = 0; d < DD; d++) {
            float4 xa = *(const float4*)&xsT[d * 20 + tr * 4];
            float2 w  = *(const float2*)&Ww[(size_t)d * DD + c];
            acc[0][0] += xa.x * w.x; acc[0][1] += xa.x * w.y;
            acc[1][0] += xa.y * w.x; acc[1][1] += xa.y * w.y;
            acc[2][0] += xa.z * w.x; acc[2][1] += xa.z * w.y;
            acc[3][0] += xa.w * w.x; acc[3][1] += xa.w * w.y;
        }
        #pragma unroll
        for (int r = 0; r < 4; r++) {
            float2 o = make_float2(acc[r][0], acc[r][1]);
            *(float2*)&g_y[(size_t)(rbase + tr * 4 + r) * DD + c] = o;
        }
    }
}

// ============================================================
// k_gemmln: h = Wsum @ y + W_b -> LayerNorm (unbiased +eps) -> ReLU
//   4 rows/block, grid 256, 320 threads (o < 300 active).
//   Writes node_out and g_A[:,50:350].
// ============================================================
__global__ __launch_bounds__(320) void k_gemmln(const float* __restrict__ Wb,
                                                const float* __restrict__ lna,
                                                const float* __restrict__ lnb,
                                                float* __restrict__ node_out) {
    __shared__ __align__(16) float wrT[SD][4];    // transposed wsum tile
    __shared__ float redA[10];
    __shared__ float redB[10];
    __shared__ float bc[2];
    int rb = blockIdx.x * 4;
    int b = rb >> 7;
    for (int t = threadIdx.x; t < 4 * SD; t += 320) {
        int r = t >> 7, j = t & 127;
        wrT[j][r] = g_wsum[(size_t)(rb + r) * SD + j];
    }
    __syncthreads();

    int o = threadIdx.x;
    float acc[4];
    #pragma unroll
    for (int r = 0; r < 4; r++) acc[r] = 0.f;
    if (o < DD) {
        const float* yb = g_y + (size_t)(b * SD) * DD + o;
        #pragma unroll 4
        for (int j = 0; j < SD; j++) {
            float v = yb[(size_t)j * DD];
            float4 w = *(const float4*)&wrT[j][0];
            acc[0] += w.x * v; acc[1] += w.y * v; acc[2] += w.z * v; acc[3] += w.w * v;
        }
        float bias = Wb[o];
        #pragma unroll
        for (int r = 0; r < 4; r++) acc[r] += bias;
    }
    float la = (o < DD) ? lna[o] : 0.f;
    float lb = (o < DD) ? lnb[o] : 0.f;
    int lane = threadIdx.x & 31, wid = threadIdx.x >> 5;

    for (int r = 0; r < 4; r++) {
        float h = (o < DD) ? acc[r] : 0.f;
        float s1 = h, s2 = h * h;
        #pragma unroll
        for (int off = 16; off > 0; off >>= 1) {
            s1 += __shfl_down_sync(0xffffffffu, s1, off);
            s2 += __shfl_down_sync(0xffffffffu, s2, off);
        }
        if (lane == 0) { redA[wid] = s1; redB[wid] = s2; }
        __syncthreads();
        if (threadIdx.x == 0) {
            float t1 = 0.f, t2 = 0.f;
            #pragma unroll
            for (int w = 0; w < 10; w++) { t1 += redA[w]; t2 += redB[w]; }
            bc[0] = t1; bc[1] = t2;
        }
        __syncthreads();
        float mean = bc[0] * (1.0f / (float)DD);
        float var = (bc[1] - (float)DD * mean * mean) * (1.0f / (float)(DD - 1));
        var = fmaxf(var, 0.f);
        float inv = 1.0f / (sqrtf(var) + EPSV);
        if (o < DD) {
            float nv = la * (acc[r] - mean) * inv + lb;
            nv = fmaxf(nv, 0.f);
            int gi = rb + r;
            g_A[(size_t)gi * AK + 50 + o] = nv;
            if (node_out) node_out[(size_t)gi * DD + o] = nv;
        }
        __syncthreads();
    }
}

// ============================================================
// k_terms: combined refine GEMM  [1024 x 352] @ [352 x 128] -> tJ | tI
//   grid 256, 128 thr, tile 4 rows x 128 cols, thread = 1 row x 4 cols.
// ============================================================
__global__ __launch_bounds__(128) void k_terms() {
    __shared__ __align__(16) float Ws[32][WCC];   // 16 KB
    __shared__ float As[4][32];
    int rbase = blockIdx.x * 4;
    int r = threadIdx.x >> 5;                     // 0..3
    int lane = threadIdx.x & 31;
    int c0 = lane * 4;
    float a0 = 0.f, a1 = 0.f, a2 = 0.f, a3 = 0.f;

    for (int k0 = 0; k0 < AK; k0 += 32) {
        __syncthreads();
        #pragma unroll
        for (int p = 0; p < 8; p++) {
            int kk = r + p * 4;
            *(float4*)&Ws[kk][c0] = *(const float4*)&g_Wc[(size_t)(k0 + kk) * WCC + c0];
        }
        As[r][lane] = g_A[(size_t)(rbase + r) * AK + k0 + lane];
        __syncthreads();
        #pragma unroll
        for (int kk = 0; kk < 32; kk++) {
            float a = As[r][kk];
            float4 w = *(const float4*)&Ws[kk][c0];
            a0 += a * w.x; a1 += a * w.y; a2 += a * w.z; a3 += a * w.w;
        }
    }

    int row = rbase + r;
    if (c0 < DED) {
        float* dst = g_tJ + (size_t)row * DED + c0;
        dst[0] = a0;
        if (c0 + 1 < DED) dst[1] = a1;
        if (c0 + 2 < DED) dst[2] = a2;
        if (c0 + 3 < DED) dst[3] = a3;
    } else if (c0 >= 64 && c0 < 64 + DED) {
        int cc = c0 - 64;
        float* dst = g_tI + (size_t)row * DED + cc;
        dst[0] = a0;
        if (cc + 1 < DED) dst[1] = a1;
        if (cc + 2 < DED) dst[2] = a2;
        if (cc + 3 < DED) dst[3] = a3;
    }
}

// ============================================================
// k_edge: edge_out[row,o] = adj[row,:50]@Wa + termJ[b,j] + termI[b,i] + rb
//   Tile: 64 rows x 64 cols (50 valid), 128 threads, thread = 4x8.
// ============================================================
__global__ __launch_bounds__(128) void k_edge(const float* __restrict__ wadj,
                                              const float* __restrict__ rW,
                                              const float* __restrict__ rb,
                                              float* __restrict__ eout) {
    __shared__ float adjS[64][52];
    __shared__ __align__(16) float WaS[ED][64];
    __shared__ float tJS[64][DED];
    __shared__ float cI[64];
    int rbase = blockIdx.x * 64;
    int b = rbase >> 14;
    int i = (rbase >> 7) & 127;
    int jbase = rbase & 127;

    for (int t = threadIdx.x; t < 64 * ED; t += 128) {
        int r = t / ED, e = t % ED;
        adjS[r][e] = wadj[(size_t)rbase * ED + t];
    }
    for (int t = threadIdx.x; t < ED * 64; t += 128) {
        int e = t >> 6, o = t & 63;
        WaS[e][o] = (o < DED) ? rW[(size_t)e * DED + o] : 0.f;
    }
    for (int t = threadIdx.x; t < 64 * DED; t += 128)
        tJS[t / DED][t % DED] = g_tJ[(size_t)(b * SD + jbase) * DED + t];
    if (threadIdx.x < 64) {
        int o = threadIdx.x;
        cI[o] = (o < DED) ? (g_tI[(size_t)(b * SD + i) * DED + o] + rb[o]) : 0.f;
    }
    __syncthreads();

    int cg = threadIdx.x & 7;
    int rg = threadIdx.x >> 3;
    int r0 = rg * 4;
    int c0 = cg * 8;

    float acc[4][8];
    #pragma unroll
    for (int r = 0; r < 4; r++)
        #pragma unroll
        for (int k = 0; k < 8; k++) acc[r][k] = 0.f;

    #pragma unroll 2
    for (int e = 0; e < ED; e++) {
        float a[4];
        #pragma unroll
        for (int r = 0; r < 4; r++) a[r] = adjS[r0 + r][e];
        float4 w0 = *(const float4*)&WaS[e][c0];
        float4 w1 = *(const float4*)&WaS[e][c0 + 4];
        float w[8] = {w0.x, w0.y, w0.z, w0.w, w1.x, w1.y, w1.z, w1.w};
        #pragma unroll
        for (int r = 0; r < 4; r++)
            #pragma unroll
            for (int k = 0; k < 8; k++) acc[r][k] += a[r] * w[k];
    }

    #pragma unroll
    for (int r = 0; r < 4; r++) {
        int row = rbase + r0 + r;
        float* orow = eout + (size_t)row * DED;
        const float* tjr = tJS[r0 + r];
        #pragma unroll
        for (int k = 0; k < 8; k++) {
            int o = c0 + k;
            if (o < DED) orow[o] = acc[r][k] + tjr[o] + cI[o];
        }
    }
}

// ============================================================
extern "C" void kernel_launch(void* const* d_in, const int* in_sizes, int n_in,
                              void* d_out, int out_size) {
    const float* wps  = (const float*)d_in[0];   // [B,S,S,E]
    const float* wadj = (const float*)d_in[1];   // [B,S,S,E]
    const float* x    = (const float*)d_in[2];   // [B,S,D]
    // d_in[3] self_loop: identity by construction -> unused
    const float* Ww   = (const float*)d_in[4];   // [D,D]
    const float* Wb   = (const float*)d_in[5];   // [D]
    const float* lna  = (const float*)d_in[6];   // [D]
    const float* lnb  = (const float*)d_in[7];   // [D]
    const float* rW   = (const float*)d_in[8];   // [750,50]
    const float* rb   = (const float*)d_in[9];   // [50]

    float* out = (float*)d_out;
    float* node_out = nullptr;
    float* edge_out;
    if (out_size >= NODE_ELEMS + EDGE_ELEMS) {
        node_out = out;
        edge_out = out + NODE_ELEMS;
    } else {
        edge_out = out + (out_size - EDGE_ELEMS);  // edge-only fallback
    }

    k_front <<<1024 + PREP_BLOCKS + XW_BLOCKS, 256>>>(wps, wadj, rW, x, Ww);
    k_gemmln<<<BD*SD/4, 320>>>(Wb, lna, lnb, node_out);
    k_terms <<<BD*SD/4, 128>>>();
    k_edge  <<<BD*SD*SD/64, 128>>>(wadj, rW, rb, edge_out);
}

// round 14
// speedup vs baseline: 1.4698x; 1.0848x over previous
#include <cuda_runtime.h>
#include <math.h>

#define BD 8
#define SD 128
#define ED 50
#define DD 300
#define DED 50
#define EPSV 1e-6f

#define NODE_ELEMS (BD*SD*DD)          // 307200
#define EDGE_ELEMS (BD*SD*SD*DED)      // 6553600

#define AK 352        // padded K for combined refine GEMM (50 diag + 300 node + 2 pad)
#define WCC 128       // padded cols: 0..49 = J, 64..113 = I

// ---- scratch (no allocation allowed) ----
__device__ float g_wsum[BD*SD*SD];       // collapsed adjacency
__device__ float g_y[BD*SD*DD];          // x @ W_w
__device__ float g_A[BD*SD*AK];          // [diag | node] packed rows
__device__ float g_Wc[AK*WCC];           // combined refine weights
__device__ float g_tJ[BD*SD*DED];
__device__ float g_tI[BD*SD*DED];

#define PREP_BLOCKS 376   // ceil((AK*WCC + BD*SD*DED)/256)
#define XW_BLOCKS   192   // (BD*SD/16)*3

// ============================================================
// k_front: three independent jobs in one launch.
//   blocks [0,1024):        Wsum[b,i,j] = mean_e softmax + (i==j)
//   blocks [1024,1400):     build g_Wc and diag part of g_A
//   blocks [1400,1592):     y = x @ W_w  (tile 16 rows x 100 cols)
// ============================================================
__global__ __launch_bounds__(256) void k_front(const float* __restrict__ wps,
                                               const float* __restrict__ wadj,
                                               const float* __restrict__ rW,
                                               const float* __restrict__ x,
                                               const float* __restrict__ Ww) {
    __shared__ __align__(16) float sm[6400];     // 25.6 KB, shared by branches
    if (blockIdx.x < 1024) {
        // ---- wsum ----
        int rbase = blockIdx.x * 128;
        const float* src = wps + (size_t)rbase * ED;
        for (int t = threadIdx.x; t < 128 * ED; t += 256) sm[t] = src[t];
        __syncthreads();
        if (threadIdx.x < 128) {
            int r = threadIdx.x;
            float s = 0.f;
            #pragma unroll
            for (int e = 0; e < ED; e++) s += sm[r * ED + e];
            int row = rbase + r;
            int j = row & 127;
            int i = (row >> 7) & 127;
            g_wsum[row] = s * (1.0f / (float)ED) + (i == j ? 1.0f : 0.0f);
        }
    } else if (blockIdx.x < 1024 + PREP_BLOCKS) {
        // ---- Wc + diag(A) prep ----
        int idx = (blockIdx.x - 1024) * 256 + threadIdx.x;
        if (idx < AK * WCC) {
            int k = idx >> 7;
            int c = idx & 127;
            float v = 0.f;
            if (k < 350) {
                if (c < DED) {
                    int row = (k < 50) ? (50 + k) : (100 + k);
                    v = rW[(size_t)row * DED + c];
                } else if (c >= 64 && c < 64 + DED) {
                    int row = (k < 50) ? (100 + k) : (400 + k);
                    v = rW[(size_t)row * DED + (c - 64)];
                }
            }
            g_Wc[idx] = v;
        } else if (idx < AK * WCC + BD * SD * DED) {
            int t = idx - AK * WCC;
            int r = t / DED, e = t % DED;
            int b = r >> 7, s = r & 127;
            g_A[(size_t)r * AK + e] = wadj[((size_t)(b * SD + s) * SD + s) * ED + e];
        }
    } else {
        // ---- xw: y = x @ W_w, tile 16 rows x 100 cols ----
        float* xsT = sm;                          // [d][r] stride 20
        int bxw = blockIdx.x - (1024 + PREP_BLOCKS);
        int rbase = (bxw / 3) * 16;
        int cbase = (bxw % 3) * 100;
        for (int t = threadIdx.x; t < 16 * DD; t += 256) {
            int r = t / DD, d = t % DD;
            xsT[d * 20 + r] = x[(size_t)(rbase + r) * DD + d];
        }
        __syncthreads();
        if (threadIdx.x >= 200) return;
        int tr = threadIdx.x / 50;     // 0..3
        int tc = threadIdx.x % 50;
        int c = cbase + tc * 2;
        float acc[4][2];
        #pragma unroll
        for (int r = 0; r < 4; r++) { acc[r][0] = 0.f; acc[r][1] = 0.f; }
        #pragma unroll 4
        for (int d = 0; d < DD; d++) {
            float4 xa = *(const float4*)&xsT[d * 20 + tr * 4];
            float2 w  = *(const float2*)&Ww[(size_t)d * DD + c];
            acc[0][0] += xa.x * w.x; acc[0][1] += xa.x * w.y;
            acc[1][0] += xa.y * w.x; acc[1][1] += xa.y * w.y;
            acc[2][0] += xa.z * w.x; acc[2][1] += xa.z * w.y;
            acc[3][0] += xa.w * w.x; acc[3][1] += xa.w * w.y;
        }
        #pragma unroll
        for (int r = 0; r < 4; r++) {
            float2 o = make_float2(acc[r][0], acc[r][1]);
            *(float2*)&g_y[(size_t)(rbase + tr * 4 + r) * DD + c] = o;
        }
    }
}

// ============================================================
// k_gemmln: h = Wsum @ y + W_b -> LayerNorm (unbiased +eps) -> ReLU
//   4 rows/block, grid 256, 320 threads (o < 300 active).
// ============================================================
__global__ __launch_bounds__(320) void k_gemmln(const float* __restrict__ Wb,
                                                const float* __restrict__ lna,
                                                const float* __restrict__ lnb,
                                                float* __restrict__ node_out) {
    __shared__ __align__(16) float wrT[SD][4];
    __shared__ float redA[10];
    __shared__ float redB[10];
    __shared__ float bc[2];
    int rb = blockIdx.x * 4;
    int b = rb >> 7;
    for (int t = threadIdx.x; t < 4 * SD; t += 320) {
        int r = t >> 7, j = t & 127;
        wrT[j][r] = g_wsum[(size_t)(rb + r) * SD + j];
    }
    __syncthreads();

    int o = threadIdx.x;
    float acc[4];
    #pragma unroll
    for (int r = 0; r < 4; r++) acc[r] = 0.f;
    if (o < DD) {
        const float* yb = g_y + (size_t)(b * SD) * DD + o;
        #pragma unroll 4
        for (int j = 0; j < SD; j++) {
            float v = yb[(size_t)j * DD];
            float4 w = *(const float4*)&wrT[j][0];
            acc[0] += w.x * v; acc[1] += w.y * v; acc[2] += w.z * v; acc[3] += w.w * v;
        }
        float bias = Wb[o];
        #pragma unroll
        for (int r = 0; r < 4; r++) acc[r] += bias;
    }
    float la = (o < DD) ? lna[o] : 0.f;
    float lb = (o < DD) ? lnb[o] : 0.f;
    int lane = threadIdx.x & 31, wid = threadIdx.x >> 5;

    for (int r = 0; r < 4; r++) {
        float h = (o < DD) ? acc[r] : 0.f;
        float s1 = h, s2 = h * h;
        #pragma unroll
        for (int off = 16; off > 0; off >>= 1) {
            s1 += __shfl_down_sync(0xffffffffu, s1, off);
            s2 += __shfl_down_sync(0xffffffffu, s2, off);
        }
        if (lane == 0) { redA[wid] = s1; redB[wid] = s2; }
        __syncthreads();
        if (threadIdx.x == 0) {
            float t1 = 0.f, t2 = 0.f;
            #pragma unroll
            for (int w = 0; w < 10; w++) { t1 += redA[w]; t2 += redB[w]; }
            bc[0] = t1; bc[1] = t2;
        }
        __syncthreads();
        float mean = bc[0] * (1.0f / (float)DD);
        float var = (bc[1] - (float)DD * mean * mean) * (1.0f / (float)(DD - 1));
        var = fmaxf(var, 0.f);
        float inv = 1.0f / (sqrtf(var) + EPSV);
        if (o < DD) {
            float nv = la * (acc[r] - mean) * inv + lb;
            nv = fmaxf(nv, 0.f);
            int gi = rb + r;
            g_A[(size_t)gi * AK + 50 + o] = nv;
            if (node_out) node_out[(size_t)gi * DD + o] = nv;
        }
        __syncthreads();
    }
}

// ============================================================
// k_terms: combined refine GEMM  [1024 x 352] @ [352 x 128] -> tJ | tI
//   grid 256, 128 thr, tile 4 rows x 128 cols, thread = 1 row x 4 cols.
// ============================================================
__global__ __launch_bounds__(128) void k_terms() {
    __shared__ __align__(16) float Ws[32][WCC];
    __shared__ float As[4][32];
    int rbase = blockIdx.x * 4;
    int r = threadIdx.x >> 5;                     // 0..3
    int lane = threadIdx.x & 31;
    int c0 = lane * 4;
    float a0 = 0.f, a1 = 0.f, a2 = 0.f, a3 = 0.f;

    for (int k0 = 0; k0 < AK; k0 += 32) {
        __syncthreads();
        #pragma unroll
        for (int p = 0; p < 8; p++) {
            int kk = r + p * 4;
            *(float4*)&Ws[kk][c0] = *(const float4*)&g_Wc[(size_t)(k0 + kk) * WCC + c0];
        }
        As[r][lane] = g_A[(size_t)(rbase + r) * AK + k0 + lane];
        __syncthreads();
        #pragma unroll
        for (int kk = 0; kk < 32; kk++) {
            float a = As[r][kk];
            float4 w = *(const float4*)&Ws[kk][c0];
            a0 += a * w.x; a1 += a * w.y; a2 += a * w.z; a3 += a * w.w;
        }
    }

    int row = rbase + r;
    if (c0 < DED) {
        float* dst = g_tJ + (size_t)row * DED + c0;
        dst[0] = a0;
        if (c0 + 1 < DED) dst[1] = a1;
        if (c0 + 2 < DED) dst[2] = a2;
        if (c0 + 3 < DED) dst[3] = a3;
    } else if (c0 >= 64 && c0 < 64 + DED) {
        int cc = c0 - 64;
        float* dst = g_tI + (size_t)row * DED + cc;
        dst[0] = a0;
        if (cc + 1 < DED) dst[1] = a1;
        if (cc + 2 < DED) dst[2] = a2;
        if (cc + 3 < DED) dst[3] = a3;
    }
}

// ============================================================
// k_edge: edge_out[row,o] = adj[row,:50]@Wa + termJ[b,j] + termI[b,i] + rb
//   Tile: 128 rows (all j of one (b,i)) x 64 cols.  128 thr, thread = 8x8.
//   Per e: 4 x LDS128 -> 64 FMA.  grid 1024.
// ============================================================
#define ATS 136   // adjT row stride in floats (16B-aligned)
__global__ __launch_bounds__(128) void k_edge(const float* __restrict__ wadj,
                                              const float* __restrict__ rW,
                                              const float* __restrict__ rb,
                                              float* __restrict__ eout) {
    __shared__ __align__(16) float adjT[ED][ATS];   // 27.2 KB, [e][row]
    __shared__ __align__(16) float WaS[ED][64];     // 12.8 KB
    __shared__ float cI[64];
    int rbase = blockIdx.x * 128;        // rows (b,i,j) with fixed (b,i)
    int b = rbase >> 14;
    int i = (rbase >> 7) & 127;

    // stage adj transposed: adjT[e][j]
    for (int t = threadIdx.x; t < 128 * ED; t += 128) {
        int row = t / ED, e = t % ED;
        adjT[e][row] = wadj[(size_t)rbase * ED + t];
    }
    // stage Wa (zero-padded to 64 cols)
    for (int t = threadIdx.x; t < ED * 64; t += 128) {
        int e = t >> 6, o = t & 63;
        WaS[e][o] = (o < DED) ? rW[(size_t)e * DED + o] : 0.f;
    }
    if (threadIdx.x < 64) {
        int o = threadIdx.x;
        cI[o] = (o < DED) ? (g_tI[(size_t)(b * SD + i) * DED + o] + rb[o]) : 0.f;
    }
    __syncthreads();

    int rg = threadIdx.x >> 3;    // 0..15 -> rows rg*8..+8
    int cg = threadIdx.x & 7;     // 0..7  -> cols cg*8..+8
    int r0 = rg * 8;
    int c0 = cg * 8;

    float acc[8][8];
    #pragma unroll
    for (int r = 0; r < 8; r++)
        #pragma unroll
        for (int k = 0; k < 8; k++) acc[r][k] = 0.f;

    #pragma unroll 2
    for (int e = 0; e < ED; e++) {
        float4 a0 = *(const float4*)&adjT[e][r0];
        float4 a1 = *(const float4*)&adjT[e][r0 + 4];
        float4 w0 = *(const float4*)&WaS[e][c0];
        float4 w1 = *(const float4*)&WaS[e][c0 + 4];
        float a[8] = {a0.x, a0.y, a0.z, a0.w, a1.x, a1.y, a1.z, a1.w};
        float w[8] = {w0.x, w0.y, w0.z, w0.w, w1.x, w1.y, w1.z, w1.w};
        #pragma unroll
        for (int r = 0; r < 8; r++)
            #pragma unroll
            for (int k = 0; k < 8; k++) acc[r][k] += a[r] * w[k];
    }

    // epilogue: + termJ[b,j] + (termI[b,i] + rb)
    #pragma unroll
    for (int r = 0; r < 8; r++) {
        int j = r0 + r;
        float* orow = eout + (size_t)(rbase + j) * DED;
        const float* tj = g_tJ + (size_t)(b * SD + j) * DED;
        #pragma unroll
        for (int k = 0; k < 8; k++) {
            int o = c0 + k;
            if (o < DED) orow[o] = acc[r][k] + __ldg(&tj[o]) + cI[o];
        }
    }
}

// ============================================================
extern "C" void kernel_launch(void* const* d_in, const int* in_sizes, int n_in,
                              void* d_out, int out_size) {
    const float* wps  = (const float*)d_in[0];   // [B,S,S,E]
    const float* wadj = (const float*)d_in[1];   // [B,S,S,E]
    const float* x    = (const float*)d_in[2];   // [B,S,D]
    // d_in[3] self_loop: identity by construction -> unused
    const float* Ww   = (const float*)d_in[4];   // [D,D]
    const float* Wb   = (const float*)d_in[5];   // [D]
    const float* lna  = (const float*)d_in[6];   // [D]
    const float* lnb  = (const float*)d_in[7];   // [D]
    const float* rW   = (const float*)d_in[8];   // [750,50]
    const float* rb   = (const float*)d_in[9];   // [50]

    float* out = (float*)d_out;
    float* node_out = nullptr;
    float* edge_out;
    if (out_size >= NODE_ELEMS + EDGE_ELEMS) {
        node_out = out;
        edge_out = out + NODE_ELEMS;
    } else {
        edge_out = out + (out_size - EDGE_ELEMS);  // edge-only fallback
    }

    k_front <<<1024 + PREP_BLOCKS + XW_BLOCKS, 256>>>(wps, wadj, rW, x, Ww);
    k_gemmln<<<BD*SD/4, 320>>>(Wb, lna, lnb, node_out);
    k_terms <<<BD*SD/4, 128>>>();
    k_edge  <<<BD*SD*SD/128, 128>>>(wadj, rW, rb, edge_out);
}

// round 15
// speedup vs baseline: 1.7298x; 1.1769x over previous
#include <cuda_runtime.h>
#include <math.h>

#define BD 8
#define SD 128
#define ED 50
#define DD 300
#define DED 50
#define EPSV 1e-6f

#define NODE_ELEMS (BD*SD*DD)          // 307200
#define EDGE_ELEMS (BD*SD*SD*DED)      // 6553600

#define AK 352        // padded K for combined refine GEMM (50 diag + 300 node + 2 pad)
#define WCC 128       // padded cols: 0..49 = J, 64..113 = I

// ---- scratch (no allocation allowed) ----
__device__ float g_wsum[BD*SD*SD];       // collapsed adjacency
__device__ float g_y[BD*SD*DD];          // x @ W_w
__device__ float g_A[BD*SD*AK];          // [diag | node] packed rows
__device__ float g_Wc[AK*WCC];           // combined refine weights
__device__ float g_tJ[BD*SD*DED];
__device__ float g_tI[BD*SD*DED];

#define PREP_BLOCKS 376   // ceil((AK*WCC + BD*SD*DED)/256)
#define XW_BLOCKS   192   // (BD*SD/16)*3

// ============================================================
// k_front: three independent jobs in one launch.
//   blocks [0,1024):        Wsum[b,i,j] = mean_e softmax + (i==j)
//   blocks [1024,1400):     build g_Wc and diag part of g_A
//   blocks [1400,1592):     y = x @ W_w  (tile 16 rows x 100 cols)
// ============================================================
__global__ __launch_bounds__(256) void k_front(const float* __restrict__ wps,
                                               const float* __restrict__ wadj,
                                               const float* __restrict__ rW,
                                               const float* __restrict__ x,
                                               const float* __restrict__ Ww) {
    __shared__ __align__(16) float sm[6400];     // 25.6 KB, shared by branches
    if (blockIdx.x < 1024) {
        // ---- wsum ----
        int rbase = blockIdx.x * 128;
        const float* src = wps + (size_t)rbase * ED;
        for (int t = threadIdx.x; t < 128 * ED; t += 256) sm[t] = src[t];
        __syncthreads();
        if (threadIdx.x < 128) {
            int r = threadIdx.x;
            float s = 0.f;
            #pragma unroll
            for (int e = 0; e < ED; e++) s += sm[r * ED + e];
            int row = rbase + r;
            int j = row & 127;
            int i = (row >> 7) & 127;
            g_wsum[row] = s * (1.0f / (float)ED) + (i == j ? 1.0f : 0.0f);
        }
    } else if (blockIdx.x < 1024 + PREP_BLOCKS) {
        // ---- Wc + diag(A) prep ----
        int idx = (blockIdx.x - 1024) * 256 + threadIdx.x;
        if (idx < AK * WCC) {
            int k = idx >> 7;
            int c = idx & 127;
            float v = 0.f;
            if (k < 350) {
                if (c < DED) {
                    int row = (k < 50) ? (50 + k) : (100 + k);
                    v = rW[(size_t)row * DED + c];
                } else if (c >= 64 && c < 64 + DED) {
                    int row = (k < 50) ? (100 + k) : (400 + k);
                    v = rW[(size_t)row * DED + (c - 64)];
                }
            }
            g_Wc[idx] = v;
        } else if (idx < AK * WCC + BD * SD * DED) {
            int t = idx - AK * WCC;
            int r = t / DED, e = t % DED;
            int b = r >> 7, s = r & 127;
            g_A[(size_t)r * AK + e] = wadj[((size_t)(b * SD + s) * SD + s) * ED + e];
        }
    } else {
        // ---- xw: y = x @ W_w, tile 16 rows x 100 cols ----
        float* xsT = sm;                          // [d][r] stride 20
        int bxw = blockIdx.x - (1024 + PREP_BLOCKS);
        int rbase = (bxw / 3) * 16;
        int cbase = (bxw % 3) * 100;
        for (int t = threadIdx.x; t < 16 * DD; t += 256) {
            int r = t / DD, d = t % DD;
            xsT[d * 20 + r] = x[(size_t)(rbase + r) * DD + d];
        }
        __syncthreads();
        if (threadIdx.x >= 200) return;
        int tr = threadIdx.x / 50;     // 0..3
        int tc = threadIdx.x % 50;
        int c = cbase + tc * 2;
        float acc[4][2];
        #pragma unroll
        for (int r = 0; r < 4; r++) { acc[r][0] = 0.f; acc[r][1] = 0.f; }
        #pragma unroll 4
        for (int d = 0; d < DD; d++) {
            float4 xa = *(const float4*)&xsT[d * 20 + tr * 4];
            float2 w  = *(const float2*)&Ww[(size_t)d * DD + c];
            acc[0][0] += xa.x * w.x; acc[0][1] += xa.x * w.y;
            acc[1][0] += xa.y * w.x; acc[1][1] += xa.y * w.y;
            acc[2][0] += xa.z * w.x; acc[2][1] += xa.z * w.y;
            acc[3][0] += xa.w * w.x; acc[3][1] += xa.w * w.y;
        }
        #pragma unroll
        for (int r = 0; r < 4; r++) {
            float2 o = make_float2(acc[r][0], acc[r][1]);
            *(float2*)&g_y[(size_t)(rbase + tr * 4 + r) * DD + c] = o;
        }
    }
}

// ============================================================
// k_gemmln: h = Wsum @ y + W_b -> LayerNorm (unbiased +eps) -> ReLU
//   4 rows/block, grid 256, 320 threads (o < 300 active).
// ============================================================
__global__ __launch_bounds__(320) void k_gemmln(const float* __restrict__ Wb,
                                                const float* __restrict__ lna,
                                                const float* __restrict__ lnb,
                                                float* __restrict__ node_out) {
    __shared__ __align__(16) float wrT[SD][4];
    __shared__ float redA[10];
    __shared__ float redB[10];
    __shared__ float bc[2];
    int rb = blockIdx.x * 4;
    int b = rb >> 7;
    for (int t = threadIdx.x; t < 4 * SD; t += 320) {
        int r = t >> 7, j = t & 127;
        wrT[j][r] = g_wsum[(size_t)(rb + r) * SD + j];
    }
    __syncthreads();

    int o = threadIdx.x;
    float acc[4];
    #pragma unroll
    for (int r = 0; r < 4; r++) acc[r] = 0.f;
    if (o < DD) {
        const float* yb = g_y + (size_t)(b * SD) * DD + o;
        #pragma unroll 4
        for (int j = 0; j < SD; j++) {
            float v = yb[(size_t)j * DD];
            float4 w = *(const float4*)&wrT[j][0];
            acc[0] += w.x * v; acc[1] += w.y * v; acc[2] += w.z * v; acc[3] += w.w * v;
        }
        float bias = Wb[o];
        #pragma unroll
        for (int r = 0; r < 4; r++) acc[r] += bias;
    }
    float la = (o < DD) ? lna[o] : 0.f;
    float lb = (o < DD) ? lnb[o] : 0.f;
    int lane = threadIdx.x & 31, wid = threadIdx.x >> 5;

    for (int r = 0; r < 4; r++) {
        float h = (o < DD) ? acc[r] : 0.f;
        float s1 = h, s2 = h * h;
        #pragma unroll
        for (int off = 16; off > 0; off >>= 1) {
            s1 += __shfl_down_sync(0xffffffffu, s1, off);
            s2 += __shfl_down_sync(0xffffffffu, s2, off);
        }
        if (lane == 0) { redA[wid] = s1; redB[wid] = s2; }
        __syncthreads();
        if (threadIdx.x == 0) {
            float t1 = 0.f, t2 = 0.f;
            #pragma unroll
            for (int w = 0; w < 10; w++) { t1 += redA[w]; t2 += redB[w]; }
            bc[0] = t1; bc[1] = t2;
        }
        __syncthreads();
        float mean = bc[0] * (1.0f / (float)DD);
        float var = (bc[1] - (float)DD * mean * mean) * (1.0f / (float)(DD - 1));
        var = fmaxf(var, 0.f);
        float inv = 1.0f / (sqrtf(var) + EPSV);
        if (o < DD) {
            float nv = la * (acc[r] - mean) * inv + lb;
            nv = fmaxf(nv, 0.f);
            int gi = rb + r;
            g_A[(size_t)gi * AK + 50 + o] = nv;
            if (node_out) node_out[(size_t)gi * DD + o] = nv;
        }
        __syncthreads();
    }
}

// ============================================================
// k_terms: combined refine GEMM  [1024 x 352] @ [352 x 128] -> tJ | tI
//   grid 256, 128 thr, tile 4 rows x 128 cols, thread = 1 row x 4 cols.
// ============================================================
__global__ __launch_bounds__(128) void k_terms() {
    __shared__ __align__(16) float Ws[32][WCC];
    __shared__ float As[4][32];
    int rbase = blockIdx.x * 4;
    int r = threadIdx.x >> 5;                     // 0..3
    int lane = threadIdx.x & 31;
    int c0 = lane * 4;
    float a0 = 0.f, a1 = 0.f, a2 = 0.f, a3 = 0.f;

    for (int k0 = 0; k0 < AK; k0 += 32) {
        __syncthreads();
        #pragma unroll
        for (int p = 0; p < 8; p++) {
            int kk = r + p * 4;
            *(float4*)&Ws[kk][c0] = *(const float4*)&g_Wc[(size_t)(k0 + kk) * WCC + c0];
        }
        As[r][lane] = g_A[(size_t)(rbase + r) * AK + k0 + lane];
        __syncthreads();
        #pragma unroll
        for (int kk = 0; kk < 32; kk++) {
            float a = As[r][kk];
            float4 w = *(const float4*)&Ws[kk][c0];
            a0 += a * w.x; a1 += a * w.y; a2 += a * w.z; a3 += a * w.w;
        }
    }

    int row = rbase + r;
    if (c0 < DED) {
        float* dst = g_tJ + (size_t)row * DED + c0;
        dst[0] = a0;
        if (c0 + 1 < DED) dst[1] = a1;
        if (c0 + 2 < DED) dst[2] = a2;
        if (c0 + 3 < DED) dst[3] = a3;
    } else if (c0 >= 64 && c0 < 64 + DED) {
        int cc = c0 - 64;
        float* dst = g_tI + (size_t)row * DED + cc;
        dst[0] = a0;
        if (cc + 1 < DED) dst[1] = a1;
        if (cc + 2 < DED) dst[2] = a2;
        if (cc + 3 < DED) dst[3] = a3;
    }
}

// ============================================================
// k_edge: edge_out[row,o] = adj[row,:50]@Wa + termJ[b,j] + termI[b,i] + rb
//   Tile: 128 rows (all j of one (b,i)) x 64 cols.  256 thr, thread = 8x4.
//   Per e: 3 x LDS128 -> 32 FMA.  grid 1024.  Epilogue float2 ld/st.
// ============================================================
#define ATS 136   // adjT row stride in floats (16B-aligned)
__global__ __launch_bounds__(256) void k_edge(const float* __restrict__ wadj,
                                              const float* __restrict__ rW,
                                              const float* __restrict__ rb,
                                              float* __restrict__ eout) {
    __shared__ __align__(16) float adjT[ED][ATS];   // 27.2 KB, [e][row]
    __shared__ __align__(16) float WaS[ED][64];     // 12.8 KB
    __shared__ float cI[64];
    int rbase = blockIdx.x * 128;        // rows (b,i,j) with fixed (b,i)
    int b = rbase >> 14;
    int i = (rbase >> 7) & 127;

    // stage adj transposed: adjT[e][j]
    for (int t = threadIdx.x; t < 128 * ED; t += 256) {
        int row = t / ED, e = t % ED;
        adjT[e][row] = wadj[(size_t)rbase * ED + t];
    }
    // stage Wa (zero-padded to 64 cols)
    for (int t = threadIdx.x; t < ED * 64; t += 256) {
        int e = t >> 6, o = t & 63;
        WaS[e][o] = (o < DED) ? rW[(size_t)e * DED + o] : 0.f;
    }
    if (threadIdx.x < 64) {
        int o = threadIdx.x;
        cI[o] = (o < DED) ? (g_tI[(size_t)(b * SD + i) * DED + o] + rb[o]) : 0.f;
    }
    __syncthreads();

    int rg = threadIdx.x >> 4;    // 0..15 -> rows rg*8..+8
    int cg = threadIdx.x & 15;    // 0..15 -> cols cg*4..+4
    int r0 = rg * 8;
    int c0 = cg * 4;

    float acc[8][4];
    #pragma unroll
    for (int r = 0; r < 8; r++)
        #pragma unroll
        for (int k = 0; k < 4; k++) acc[r][k] = 0.f;

    #pragma unroll 5
    for (int e = 0; e < ED; e++) {
        float4 a0 = *(const float4*)&adjT[e][r0];
        float4 a1 = *(const float4*)&adjT[e][r0 + 4];
        float4 w  = *(const float4*)&WaS[e][c0];
        float a[8] = {a0.x, a0.y, a0.z, a0.w, a1.x, a1.y, a1.z, a1.w};
        #pragma unroll
        for (int r = 0; r < 8; r++) {
            acc[r][0] += a[r] * w.x;
            acc[r][1] += a[r] * w.y;
            acc[r][2] += a[r] * w.z;
            acc[r][3] += a[r] * w.w;
        }
    }

    // epilogue: + termJ[b,j] + (termI[b,i] + rb), float2 granularity
    if (c0 < DED) {                       // cg <= 12 active
        bool pair1_valid = (c0 + 2 < DED);  // cols c0+2,c0+3 (cg=12: 50,51 invalid)
        float2 ci0 = make_float2(cI[c0], cI[c0 + 1]);
        float2 ci1 = make_float2(cI[c0 + 2], cI[c0 + 3]);
        #pragma unroll
        for (int r = 0; r < 8; r++) {
            int j = r0 + r;
            const float2* tj2 = (const float2*)(g_tJ + (size_t)(b * SD + j) * DED + c0);
            float* orow = eout + (size_t)(rbase + j) * DED + c0;
            float2 t0 = __ldg(&tj2[0]);
            float2 o0 = make_float2(acc[r][0] + t0.x + ci0.x,
                                    acc[r][1] + t0.y + ci0.y);
            *(float2*)&orow[0] = o0;
            if (pair1_valid) {
                float2 t1 = __ldg(&tj2[1]);
                float2 o1 = make_float2(acc[r][2] + t1.x + ci1.x,
                                        acc[r][3] + t1.y + ci1.y);
                *(float2*)&orow[2] = o1;
            }
        }
    }
}

// ============================================================
extern "C" void kernel_launch(void* const* d_in, const int* in_sizes, int n_in,
                              void* d_out, int out_size) {
    const float* wps  = (const float*)d_in[0];   // [B,S,S,E]
    const float* wadj = (const float*)d_in[1];   // [B,S,S,E]
    const float* x    = (const float*)d_in[2];   // [B,S,D]
    // d_in[3] self_loop: identity by construction -> unused
    const float* Ww   = (const float*)d_in[4];   // [D,D]
    const float* Wb   = (const float*)d_in[5];   // [D]
    const float* lna  = (const float*)d_in[6];   // [D]
    const float* lnb  = (const float*)d_in[7];   // [D]
    const float* rW   = (const float*)d_in[8];   // [750,50]
    const float* rb   = (const float*)d_in[9];   // [50]

    float* out = (float*)d_out;
    float* node_out = nullptr;
    float* edge_out;
    if (out_size >= NODE_ELEMS + EDGE_ELEMS) {
        node_out = out;
        edge_out = out + NODE_ELEMS;
    } else {
        edge_out = out + (out_size - EDGE_ELEMS);  // edge-only fallback
    }

    k_front <<<1024 + PREP_BLOCKS + XW_BLOCKS, 256>>>(wps, wadj, rW, x, Ww);
    k_gemmln<<<BD*SD/4, 320>>>(Wb, lna, lnb, node_out);
    k_terms <<<BD*SD/4, 128>>>();
    k_edge  <<<BD*SD*SD/128, 256>>>(wadj, rW, rb, edge_out);
}